// round 11
// baseline (speedup 1.0000x reference)
#include <cuda_runtime.h>
#include <stdint.h>

// BackEdgeConv2d: out = x * !(5 <= boxcount7x7(x >= 128/255, reflect-pad) <= 19)
// Barrier-free warp-autonomous strips + cp.async 8-stage smem ring (depth-5
// pipeline, register-free MLP). Epilogue x comes from the ring (no reload).
// Vertical window via bit-history registers; horizontal 7-tap via shfl+SWAR.

static constexpr int W     = 1024;
static constexpr int HB    = 32;           // output rows per block
static constexpr int WORDS = W / 4;        // 256 words per row
static constexpr int NT    = 288;          // 9 warps
static constexpr int D     = 8;            // smem ring stages (power of 2)

// bits of float32(128/255) = 0x3F008081; K = thresh-1 (sign trick, x >= 0)
static constexpr uint32_t KTH = 0x3F008081u - 1u;

__device__ __forceinline__ uint32_t prmt(uint32_t a, uint32_t b, uint32_t s)
{
    uint32_t d;
    asm("prmt.b32 %0, %1, %2, %3;" : "=r"(d) : "r"(a), "r"(b), "r"(s));
    return d;
}

// 4 floats -> packed 0/1 bytes (byte i = pixel >= thresh)
__device__ __forceinline__ uint32_t binz(uint4 v)
{
    uint32_t s0 = KTH - v.x, s1 = KTH - v.y, s2 = KTH - v.z, s3 = KTH - v.w;
    uint32_t p01 = prmt(s0, s1, 0x00FB);   // (sgn0, sgn1, -, -)
    uint32_t p23 = prmt(s2, s3, 0x00FB);
    return prmt(p01, p23, 0x5410) & 0x01010101u;
}

__device__ __forceinline__ int refl(int g)
{
    g = (g < 0) ? -g : g;
    return (g > W - 1) ? (2 * (W - 1) - g) : g;
}

__device__ __forceinline__ void cpa16(uint32_t saddr, const void* gaddr)
{
    asm volatile("cp.async.cg.shared.global [%0], [%1], 16;\n"
                 :: "r"(saddr), "l"(gaddr));
    asm volatile("cp.async.commit_group;\n");
}
template<int N>
__device__ __forceinline__ void cpwait()
{
    asm volatile("cp.async.wait_group %0;\n" :: "n"(N));
}

template<bool EDGE>
__device__ __forceinline__ void run_band(
    const uint4* __restrict__ xi, uint4* __restrict__ xo,
    uint4 (&ring)[D][NT], uint32_t sbase, int tid,
    int y0, int w_idx, int l_idx, bool active, bool ledge, bool redge)
{
    // pipeline index j <-> image row y0-3+j; stage = j & 7
    auto issue = [&](int j) {
        int g = y0 - 3 + j;
        if (EDGE) g = refl(g);
        cpa16(sbase + (uint32_t)(j & (D - 1)) * (NT * 16),
              &xi[(size_t)g * WORDS + l_idx]);
    };

    // ---- prologue: rows y0-3..y0+2 (j=0..5), drain, warm up window ----
    #pragma unroll
    for (int j = 0; j < 6; ++j) issue(j);
    cpwait<0>();
    uint32_t hist = 0, vsum = 0;
    #pragma unroll
    for (int j = 0; j < 6; ++j) {
        uint32_t b = binz(ring[j][tid]);
        vsum += b;
        hist = (hist << 1) | b;
    }
    // fill pipeline: rows y0+3..y0+7 (j=6..10), 5 groups pending
    #pragma unroll
    for (int j = 6; j < 11; ++j) issue(j);

    for (int y = 0; y < HB; ++y) {
        cpwait<4>();                              // row y+3 (j=y+6) landed
        uint32_t b = binz(ring[(y + 6) & (D - 1)][tid]);
        hist = ((hist << 1) | b) & 0x7F7F7F7Fu;   // bit k = row y+3-k
        vsum += b;                                // rows y-3..y+3, bytes <= 7

        uint32_t A = __shfl_up_sync(0xFFFFFFFFu, vsum, 1);
        uint32_t C = __shfl_down_sync(0xFFFFFFFFu, vsum, 1);
        if (ledge) A = prmt(vsum, vsum, 0x1234);  // reflect (-, v3, v2, v1)
        if (redge) C = prmt(vsum, vsum, 0x0012);  // reflect (v2, v1, v0, -)
        uint32_t B = vsum;
        uint32_t c = B
            + __funnelshift_r(A, B, 8)  + __funnelshift_r(A, B, 16) + __funnelshift_r(A, B, 24)
            + __funnelshift_r(B, C, 8)  + __funnelshift_r(B, C, 16) + __funnelshift_r(B, C, 24);

        // mask byte = 0x80 where 5 <= c <= 19 (c <= 49, no carries)
        uint32_t m = (c + 0x7B7B7B7Bu) & (0x93939393u - c) & 0x80808080u;

        if (active) {
            uint4 xv = ring[(y + 3) & (D - 1)][tid];   // row y, still live in ring
            uint4 o;
            o.x = xv.x & ~prmt(m, m, 0x8888);     // sign-replicate -> 0xFFFFFFFF/0
            o.y = xv.y & ~prmt(m, m, 0x9999);
            o.z = xv.z & ~prmt(m, m, 0xAAAA);
            o.w = xv.w & ~prmt(m, m, 0xBBBB);
            __stcs(&xo[(size_t)(y0 + y) * WORDS + w_idx], o);
        }

        vsum -= (hist >> 6) & 0x01010101u;        // drop row y-3
        issue(y + 11);  // row y+8 -> stage (y+3)&7: row y dead, overwrite safe
    }
}

__global__ void __launch_bounds__(NT, 6)
backedge_kernel(const uint4* __restrict__ x, uint4* __restrict__ out)
{
    __shared__ uint4 ring[D][NT];                 // 36.9 KB

    const int tid  = threadIdx.x;
    const int lane = tid & 31;
    const int warp = tid >> 5;                    // 0..8
    const int w_idx = warp * 30 + lane - 1;       // output word (-1..270)
    const int l_idx = min(max(w_idx, 0), WORDS - 1);
    const bool active = (lane >= 1) && (lane <= 30) && (w_idx < WORDS);
    const bool ledge  = (w_idx == 0);
    const bool redge  = (w_idx == WORDS - 1);

    const int y0 = blockIdx.x * HB;
    const size_t off = (size_t)blockIdx.y * (size_t)W * WORDS;
    const uint4* __restrict__ xi = x + off;
    uint4* __restrict__ xo = out + off;

    const uint32_t sbase = (uint32_t)__cvta_generic_to_shared(&ring[0][tid]);

    // loads (incl. pipeline over-issue) span rows y0-3 .. y0+HB+7
    if (y0 - 3 < 0 || y0 + HB + 7 > W - 1)
        run_band<true >(xi, xo, ring, sbase, tid, y0, w_idx, l_idx, active, ledge, redge);
    else
        run_band<false>(xi, xo, ring, sbase, tid, y0, w_idx, l_idx, active, ledge, redge);
}

extern "C" void kernel_launch(void* const* d_in, const int* in_sizes, int n_in,
                              void* d_out, int out_size)
{
    const uint4* x = (const uint4*)d_in[0];
    uint4* o = (uint4*)d_out;
    const int nimg = in_sizes[0] / (W * W);       // 48 planes
    dim3 grid(W / HB, nimg);
    backedge_kernel<<<grid, NT>>>(x, o);
}

// round 14
// speedup vs baseline: 1.0835x; 1.0835x over previous
#include <cuda_runtime.h>
#include <stdint.h>

// BackEdgeConv2d: out = x * !(5 <= boxcount7x7(x >= 128/255, reflect-pad) <= 19)
// Warp-autonomous strips + cp.async 8-stage smem ring (depth-5 pipeline).
// HB=64 -> 768 blocks = ONE wave at 6 blocks/SM. Tail keeps the committed-group
// count constant with EMPTY commit_groups so wait_group<4> always drains the
// oldest real group (wait_group only bounds the count of newest pending groups).

static constexpr int W     = 1024;
static constexpr int HB    = 64;           // output rows per block (single wave)
static constexpr int WORDS = W / 4;        // 256 words per row
static constexpr int NT    = 288;          // 9 warps
static constexpr int D     = 8;            // smem ring stages (power of 2)

// bits of float32(128/255) = 0x3F008081; K = thresh-1 (sign trick, x >= 0)
static constexpr uint32_t KTH = 0x3F008081u - 1u;

__device__ __forceinline__ uint32_t prmt(uint32_t a, uint32_t b, uint32_t s)
{
    uint32_t d;
    asm("prmt.b32 %0, %1, %2, %3;" : "=r"(d) : "r"(a), "r"(b), "r"(s));
    return d;
}

// 4 floats -> packed 0/1 bytes (byte i = pixel >= thresh)
__device__ __forceinline__ uint32_t binz(uint4 v)
{
    uint32_t s0 = KTH - v.x, s1 = KTH - v.y, s2 = KTH - v.z, s3 = KTH - v.w;
    uint32_t p01 = prmt(s0, s1, 0x00FB);   // (sgn0, sgn1, -, -)
    uint32_t p23 = prmt(s2, s3, 0x00FB);
    return prmt(p01, p23, 0x5410) & 0x01010101u;
}

__device__ __forceinline__ int refl(int g)
{
    g = (g < 0) ? -g : g;
    return (g > W - 1) ? (2 * (W - 1) - g) : g;
}

__device__ __forceinline__ void cpa16(uint32_t saddr, const void* gaddr)
{
    asm volatile("cp.async.cg.shared.global [%0], [%1], 16;\n"
                 :: "r"(saddr), "l"(gaddr));
    asm volatile("cp.async.commit_group;\n");
}
__device__ __forceinline__ void cp_commit_empty()
{
    asm volatile("cp.async.commit_group;\n");   // legal: empty group
}
template<int N>
__device__ __forceinline__ void cpwait()
{
    asm volatile("cp.async.wait_group %0;\n" :: "n"(N));
}

template<bool EDGE>
__device__ __forceinline__ void run_band(
    const uint4* __restrict__ xi, uint4* __restrict__ xo,
    uint4 (&ring)[D][NT], uint32_t sbase, int tid,
    int y0, int w_idx, int l_idx, bool active, bool ledge, bool redge)
{
    // pipeline index j <-> image row y0-3+j; stage = j & 7
    auto issue = [&](int j) {
        int g = y0 - 3 + j;
        if (EDGE) g = refl(g);
        cpa16(sbase + (uint32_t)(j & (D - 1)) * (NT * 16),
              &xi[(size_t)g * WORDS + l_idx]);
    };

    // ---- prologue: rows y0-3..y0+2 (j=0..5), drain, warm up window ----
    #pragma unroll
    for (int j = 0; j < 6; ++j) issue(j);
    cpwait<0>();
    uint32_t hist = 0, vsum = 0;
    #pragma unroll
    for (int j = 0; j < 6; ++j) {
        uint32_t b = binz(ring[j][tid]);
        vsum += b;
        hist = (hist << 1) | b;
    }
    // fill pipeline: rows y0+3..y0+7 (j=6..10), 5 groups pending
    #pragma unroll
    for (int j = 6; j < 11; ++j) issue(j);

    for (int y = 0; y < HB; ++y) {
        // 5 committed-and-unwaited groups precede this wait at every iteration
        // (tail iterations substitute empty groups), so the group holding row
        // y+3 (j=y+6) is always the oldest-but-4 and is forced complete here.
        cpwait<4>();
        uint32_t b = binz(ring[(y + 6) & (D - 1)][tid]);
        hist = ((hist << 1) | b) & 0x7F7F7F7Fu;   // bit k = row y+3-k
        vsum += b;                                // rows y-3..y+3, bytes <= 7

        uint32_t A = __shfl_up_sync(0xFFFFFFFFu, vsum, 1);
        uint32_t C = __shfl_down_sync(0xFFFFFFFFu, vsum, 1);
        if (ledge) A = prmt(vsum, vsum, 0x1234);  // reflect (-, v3, v2, v1)
        if (redge) C = prmt(vsum, vsum, 0x0012);  // reflect (v2, v1, v0, -)
        uint32_t B = vsum;
        uint32_t c = B
            + __funnelshift_r(A, B, 8)  + __funnelshift_r(A, B, 16) + __funnelshift_r(A, B, 24)
            + __funnelshift_r(B, C, 8)  + __funnelshift_r(B, C, 16) + __funnelshift_r(B, C, 24);

        // mask byte = 0x80 where 5 <= c <= 19 (c <= 49, no carries)
        uint32_t m = (c + 0x7B7B7B7Bu) & (0x93939393u - c) & 0x80808080u;

        if (active) {
            uint4 xv = ring[(y + 3) & (D - 1)][tid];   // row y, still live in ring
            uint4 o;
            o.x = xv.x & ~prmt(m, m, 0x8888);     // sign-replicate -> 0xFFFFFFFF/0
            o.y = xv.y & ~prmt(m, m, 0x9999);
            o.z = xv.z & ~prmt(m, m, 0xAAAA);
            o.w = xv.w & ~prmt(m, m, 0xBBBB);
            __stcs(&xo[(size_t)(y0 + y) * WORDS + w_idx], o);
        }

        vsum -= (hist >> 6) & 0x01010101u;        // drop row y-3
        if (y <= HB - 6)
            issue(y + 11);      // row y+8 -> stage (y+3)&7 (row y dead, safe)
        else
            cp_commit_empty();  // keep committed-group cadence for wait_group<4>
    }
}

__global__ void __launch_bounds__(NT, 6)
backedge_kernel(const uint4* __restrict__ x, uint4* __restrict__ out)
{
    __shared__ uint4 ring[D][NT];                 // 36.9 KB

    const int tid  = threadIdx.x;
    const int lane = tid & 31;
    const int warp = tid >> 5;                    // 0..8
    const int w_idx = warp * 30 + lane - 1;       // output word (-1..270)
    const int l_idx = min(max(w_idx, 0), WORDS - 1);
    const bool active = (lane >= 1) && (lane <= 30) && (w_idx < WORDS);
    const bool ledge  = (w_idx == 0);
    const bool redge  = (w_idx == WORDS - 1);

    const int y0 = blockIdx.x * HB;
    const size_t off = (size_t)blockIdx.y * (size_t)W * WORDS;
    const uint4* __restrict__ xi = x + off;
    uint4* __restrict__ xo = out + off;

    const uint32_t sbase = (uint32_t)__cvta_generic_to_shared(&ring[0][tid]);

    // loads span rows y0-3 .. y0+HB+2
    if (y0 - 3 < 0 || y0 + HB + 2 > W - 1)
        run_band<true >(xi, xo, ring, sbase, tid, y0, w_idx, l_idx, active, ledge, redge);
    else
        run_band<false>(xi, xo, ring, sbase, tid, y0, w_idx, l_idx, active, ledge, redge);
}

extern "C" void kernel_launch(void* const* d_in, const int* in_sizes, int n_in,
                              void* d_out, int out_size)
{
    const uint4* x = (const uint4*)d_in[0];
    uint4* o = (uint4*)d_out;
    const int nimg = in_sizes[0] / (W * W);       // 48 planes
    dim3 grid(W / HB, nimg);                      // 16 x 48 = 768 blocks = 1 wave
    backedge_kernel<<<grid, NT>>>(x, o);
}